// round 3
// baseline (speedup 1.0000x reference)
#include <cuda_runtime.h>
#include <math.h>

#define N_TOK 4301
#define NP    4201
#define ND    100
#define D     768
#define H     12
#define HD    64
#define QSCALE 0.125f

// Scratch (allocation-free rule: __device__ globals)
__device__ float g_q[(size_t)N_TOK * D];
__device__ float g_k[(size_t)N_TOK * D];
__device__ float g_v[(size_t)N_TOK * D];
__device__ float g_o[(size_t)N_TOK * D];

// ---------------------------------------------------------------------------
// GEMM: C[M,768] = (A[M,768] @ W[768,768]^T + bias) * scale
// 128x128 tile, BK=16, 256 threads, 8x8 per thread.
// ---------------------------------------------------------------------------
#define BM 128
#define BN 128
#define BK 16

__global__ void __launch_bounds__(256) gemm_tn(
    const float* __restrict__ A, const float* __restrict__ W,
    const float* __restrict__ bias, float* __restrict__ C,
    int M, float scale)
{
    __shared__ float As[BK][BM + 4];
    __shared__ float Bs[BK][BN + 4];
    const int m0 = blockIdx.y * BM;
    const int n0 = blockIdx.x * BN;
    const int tid = threadIdx.x;
    const int ty = tid >> 4, tx = tid & 15;

    float acc[8][8];
#pragma unroll
    for (int i = 0; i < 8; i++)
#pragma unroll
        for (int j = 0; j < 8; j++) acc[i][j] = 0.f;

    for (int k0 = 0; k0 < D; k0 += BK) {
#pragma unroll
        for (int i = 0; i < 2; i++) {
            int idx = tid + 256 * i;       // 0..511 float4 slots
            int row = idx >> 2;            // 0..127
            int c4  = (idx & 3) * 4;       // 0,4,8,12
            float4 av = make_float4(0.f, 0.f, 0.f, 0.f);
            if (m0 + row < M)
                av = *(const float4*)(A + (size_t)(m0 + row) * D + k0 + c4);
            As[c4 + 0][row] = av.x; As[c4 + 1][row] = av.y;
            As[c4 + 2][row] = av.z; As[c4 + 3][row] = av.w;
            float4 bv = *(const float4*)(W + (size_t)(n0 + row) * D + k0 + c4);
            Bs[c4 + 0][row] = bv.x; Bs[c4 + 1][row] = bv.y;
            Bs[c4 + 2][row] = bv.z; Bs[c4 + 3][row] = bv.w;
        }
        __syncthreads();
#pragma unroll
        for (int kk = 0; kk < BK; kk++) {
            float a[8], b[8];
#pragma unroll
            for (int i = 0; i < 8; i++) a[i] = As[kk][ty * 8 + i];
#pragma unroll
            for (int j = 0; j < 8; j++) b[j] = Bs[kk][tx * 8 + j];
#pragma unroll
            for (int i = 0; i < 8; i++)
#pragma unroll
                for (int j = 0; j < 8; j++)
                    acc[i][j] = fmaf(a[i], b[j], acc[i][j]);
        }
        __syncthreads();
    }

    float bvals[8];
#pragma unroll
    for (int j = 0; j < 8; j++) bvals[j] = bias ? bias[n0 + tx * 8 + j] : 0.f;
#pragma unroll
    for (int i = 0; i < 8; i++) {
        int m = m0 + ty * 8 + i;
        if (m < M) {
#pragma unroll
            for (int j = 0; j < 8; j++)
                C[(size_t)m * D + n0 + tx * 8 + j] = (acc[i][j] + bvals[j]) * scale;
        }
    }
}

// ---------------------------------------------------------------------------
// Attention: one thread per query row, streaming online softmax over all keys.
// Block = 128 queries of one head. K/V tiles of 64 keys staged in shared.
// Fast path (max unchanged) avoids the accumulator rescale.
// ---------------------------------------------------------------------------
#define TQ 128
#define TK 64

__global__ void __launch_bounds__(128) attn_kernel(
    const float* __restrict__ q, const float* __restrict__ k,
    const float* __restrict__ v, float* __restrict__ o)
{
    __shared__ float Ks[TK][HD];
    __shared__ float Vs[TK][HD];
    const int h = blockIdx.y;
    const int qi = blockIdx.x * TQ + threadIdx.x;
    const bool valid = qi < N_TOK;

    float qreg[HD];
    if (valid) {
#pragma unroll
        for (int d = 0; d < HD; d += 4) {
            float4 t = *(const float4*)(q + (size_t)qi * D + h * HD + d);
            qreg[d] = t.x; qreg[d + 1] = t.y; qreg[d + 2] = t.z; qreg[d + 3] = t.w;
        }
    } else {
#pragma unroll
        for (int d = 0; d < HD; d++) qreg[d] = 0.f;
    }

    float m = -1e30f, l = 0.f;
    float acc[HD];
#pragma unroll
    for (int d = 0; d < HD; d++) acc[d] = 0.f;

    for (int t0 = 0; t0 < N_TOK; t0 += TK) {
        const int cnt = min(TK, N_TOK - t0);
#pragma unroll
        for (int i = 0; i < 8; i++) {
            int idx = threadIdx.x + 128 * i;   // 0..1023 float4 slots
            int row = idx >> 4;                // 0..63
            int c4  = (idx & 15) * 4;
            if (row < cnt) {
                *(float4*)&Ks[row][c4] = *(const float4*)(k + (size_t)(t0 + row) * D + h * HD + c4);
                *(float4*)&Vs[row][c4] = *(const float4*)(v + (size_t)(t0 + row) * D + h * HD + c4);
            }
        }
        __syncthreads();

        for (int j = 0; j < cnt; j++) {
            float s0 = 0.f, s1 = 0.f, s2 = 0.f, s3 = 0.f;
#pragma unroll
            for (int d = 0; d < HD; d += 4) {
                float4 kv = *(const float4*)&Ks[j][d];
                s0 = fmaf(qreg[d + 0], kv.x, s0);
                s1 = fmaf(qreg[d + 1], kv.y, s1);
                s2 = fmaf(qreg[d + 2], kv.z, s2);
                s3 = fmaf(qreg[d + 3], kv.w, s3);
            }
            float s = (s0 + s1) + (s2 + s3);
            if (s <= m) {
                // common path: running max unchanged
                float p = __expf(s - m);
                l += p;
#pragma unroll
                for (int d = 0; d < HD; d += 4) {
                    float4 vv = *(const float4*)&Vs[j][d];
                    acc[d + 0] = fmaf(p, vv.x, acc[d + 0]);
                    acc[d + 1] = fmaf(p, vv.y, acc[d + 1]);
                    acc[d + 2] = fmaf(p, vv.z, acc[d + 2]);
                    acc[d + 3] = fmaf(p, vv.w, acc[d + 3]);
                }
            } else {
                // new max: rescale (p == 1 here)
                float alpha = __expf(m - s);   // exp(-1e30-s) underflows to 0 on first key
                m = s;
                l = fmaf(l, alpha, 1.f);
#pragma unroll
                for (int d = 0; d < HD; d += 4) {
                    float4 vv = *(const float4*)&Vs[j][d];
                    acc[d + 0] = fmaf(acc[d + 0], alpha, vv.x);
                    acc[d + 1] = fmaf(acc[d + 1], alpha, vv.y);
                    acc[d + 2] = fmaf(acc[d + 2], alpha, vv.z);
                    acc[d + 3] = fmaf(acc[d + 3], alpha, vv.w);
                }
            }
        }
        __syncthreads();
    }

    if (valid) {
        float inv = 1.f / l;
#pragma unroll
        for (int d = 0; d < HD; d += 4) {
            float4 r;
            r.x = acc[d + 0] * inv; r.y = acc[d + 1] * inv;
            r.z = acc[d + 2] * inv; r.w = acc[d + 3] * inv;
            *(float4*)(o + (size_t)qi * D + h * HD + d) = r;
        }
    }
}

// ---------------------------------------------------------------------------
// LayerNorm (in place): one block per token row.
// ---------------------------------------------------------------------------
__global__ void __launch_bounds__(256) ln_kernel(
    float* __restrict__ o, const float* __restrict__ g, const float* __restrict__ b)
{
    const int row = blockIdx.x;
    float* p = o + (size_t)row * D;
    const int t = threadIdx.x;
    float x0 = p[t], x1 = p[t + 256], x2 = p[t + 512];
    float s = x0 + x1 + x2;
    float sq = x0 * x0 + x1 * x1 + x2 * x2;

    __shared__ float red[64];
#pragma unroll
    for (int off = 16; off > 0; off >>= 1) {
        s  += __shfl_down_sync(0xffffffffu, s, off);
        sq += __shfl_down_sync(0xffffffffu, sq, off);
    }
    int wid = t >> 5, lid = t & 31;
    if (lid == 0) { red[wid] = s; red[wid + 32] = sq; }
    __syncthreads();
    __shared__ float mu_s, rstd_s;
    if (t == 0) {
        float S = 0.f, SQ = 0.f;
#pragma unroll
        for (int i = 0; i < 8; i++) { S += red[i]; SQ += red[i + 32]; }
        float mu = S * (1.f / D);
        float var = SQ * (1.f / D) - mu * mu;
        mu_s = mu;
        rstd_s = rsqrtf(var + 1e-5f);
    }
    __syncthreads();
    float mu = mu_s, r = rstd_s;
    p[t]       = (x0 - mu) * r * g[t]       + b[t];
    p[t + 256] = (x1 - mu) * r * g[t + 256] + b[t + 256];
    p[t + 512] = (x2 - mu) * r * g[t + 512] + b[t + 512];
}

// ---------------------------------------------------------------------------
extern "C" void kernel_launch(void* const* d_in, const int* in_sizes, int n_in,
                              void* d_out, int out_size)
{
    const float* x    = (const float*)d_in[0];
    const float* wq_p = (const float*)d_in[1];
    const float* wk_p = (const float*)d_in[2];
    const float* wv_p = (const float*)d_in[3];
    const float* wq_d = (const float*)d_in[4];
    const float* wk_d = (const float*)d_in[5];
    const float* wv_d = (const float*)d_in[6];
    const float* bq_p = (const float*)d_in[7];
    const float* bv_p = (const float*)d_in[8];
    const float* bq_d = (const float*)d_in[9];
    const float* bv_d = (const float*)d_in[10];
    const float* ln_g = (const float*)d_in[11];
    const float* ln_b = (const float*)d_in[12];
    const float* wo_p = (const float*)d_in[13];
    const float* bo_p = (const float*)d_in[14];
    const float* wo_d = (const float*)d_in[15];
    const float* bo_d = (const float*)d_in[16];
    float* out = (float*)d_out;

    float *q, *k, *v, *o;
    cudaGetSymbolAddress((void**)&q, g_q);
    cudaGetSymbolAddress((void**)&k, g_k);
    cudaGetSymbolAddress((void**)&v, g_v);
    cudaGetSymbolAddress((void**)&o, g_o);

    const size_t OFF = (size_t)NP * D;
    dim3 gp(D / BN, (NP + BM - 1) / BM);   // (6, 33)
    dim3 gd(D / BN, 1);                    // 100-row tail

    // QKV projections (q scaled by 1/sqrt(HD); k has no bias)
    gemm_tn<<<gp, 256>>>(x,        wq_p, bq_p, q,        NP, QSCALE);
    gemm_tn<<<gd, 256>>>(x + OFF,  wq_d, bq_d, q + OFF,  ND, QSCALE);
    gemm_tn<<<gp, 256>>>(x,        wk_p, (const float*)nullptr, k,       NP, 1.f);
    gemm_tn<<<gd, 256>>>(x + OFF,  wk_d, (const float*)nullptr, k + OFF, ND, 1.f);
    gemm_tn<<<gp, 256>>>(x,        wv_p, bv_p, v,        NP, 1.f);
    gemm_tn<<<gd, 256>>>(x + OFF,  wv_d, bv_d, v + OFF,  ND, 1.f);

    // Attention
    dim3 ga((N_TOK + TQ - 1) / TQ, H);     // (34, 12)
    attn_kernel<<<ga, 128>>>(q, k, v, o);

    // LayerNorm (in place on o)
    ln_kernel<<<N_TOK, 256>>>(o, ln_g, ln_b);

    // Output projection
    gemm_tn<<<gp, 256>>>(o,       wo_p, bo_p, out,       NP, 1.f);
    gemm_tn<<<gd, 256>>>(o + OFF, wo_d, bo_d, out + OFF, ND, 1.f);
}

// round 4
// speedup vs baseline: 3.2945x; 3.2945x over previous
#include <cuda_runtime.h>
#include <math.h>

#define N_TOK 4301
#define NP    4201
#define ND    100
#define D     768
#define H     12
#define HD    64
#define QSCALE 0.125f

// Scratch (allocation-free rule: __device__ globals)
__device__ float g_q[(size_t)N_TOK * D];
__device__ float g_k[(size_t)N_TOK * D];
__device__ float g_v[(size_t)N_TOK * D];
__device__ float g_o[(size_t)N_TOK * D];

// ---------------------------------------------------------------------------
// tf32 helpers
// ---------------------------------------------------------------------------
__device__ __forceinline__ unsigned f2tf32(float x) {
    unsigned u;
    asm("cvt.rna.tf32.f32 %0, %1;" : "=r"(u) : "f"(x));
    return u;
}
__device__ __forceinline__ float tf32r(float x) {
    return __uint_as_float(f2tf32(x));
}
__device__ __forceinline__ void mma_tf32(float* c,
    unsigned a0, unsigned a1, unsigned a2, unsigned a3,
    unsigned b0, unsigned b1)
{
    asm volatile(
        "mma.sync.aligned.m16n8k8.row.col.f32.tf32.tf32.f32 "
        "{%0,%1,%2,%3}, {%4,%5,%6,%7}, {%8,%9}, {%0,%1,%2,%3};"
        : "+f"(c[0]), "+f"(c[1]), "+f"(c[2]), "+f"(c[3])
        : "r"(a0), "r"(a1), "r"(a2), "r"(a3), "r"(b0), "r"(b1));
}

// ---------------------------------------------------------------------------
// tf32 tensor-core GEMM: C[M,768] = (A[M,768] @ W[768,768]^T + bias) * scale
// Block 256 thr (8 warps, 2m x 4n), tile 128x128, BK=16. Warp tile 64x32.
// ---------------------------------------------------------------------------
#define GBK 16
#define GAS 20   // As stride (floats)
#define GBS 20   // Bs stride

__global__ void __launch_bounds__(256) gemm_tc(
    const float* __restrict__ A, const float* __restrict__ W,
    const float* __restrict__ bias, float* __restrict__ C,
    int M, float scale)
{
    __shared__ float As[128 * GAS];
    __shared__ float Bs[128 * GBS];
    const int m0 = blockIdx.y * 128;
    const int n0 = blockIdx.x * 128;
    const int tid = threadIdx.x;
    const int w = tid >> 5;
    const int l = tid & 31;
    const int g = l >> 2;   // row group
    const int t = l & 3;    // thread in group
    const int wm = (w >> 2) * 64;   // warp m base (0 or 64)
    const int wn = (w & 3) * 32;    // warp n base

    float acc[4][4][4];
#pragma unroll
    for (int i = 0; i < 4; i++)
#pragma unroll
        for (int j = 0; j < 4; j++)
#pragma unroll
            for (int r = 0; r < 4; r++) acc[i][j][r] = 0.f;

    for (int k0 = 0; k0 < D; k0 += GBK) {
        // fill As (m-major, k contiguous) and Bs (n-major, k contiguous)
#pragma unroll
        for (int it = 0; it < 2; it++) {
            int slot = tid + 256 * it;      // 512 float4 slots
            int row = slot >> 2;            // 0..127
            int c4 = (slot & 3) * 4;        // 0,4,8,12
            float4 av = make_float4(0.f, 0.f, 0.f, 0.f);
            if (m0 + row < M)
                av = *(const float4*)(A + (size_t)(m0 + row) * D + k0 + c4);
            av.x = tf32r(av.x); av.y = tf32r(av.y);
            av.z = tf32r(av.z); av.w = tf32r(av.w);
            *(float4*)(As + row * GAS + c4) = av;
            float4 bv = *(const float4*)(W + (size_t)(n0 + row) * D + k0 + c4);
            bv.x = tf32r(bv.x); bv.y = tf32r(bv.y);
            bv.z = tf32r(bv.z); bv.w = tf32r(bv.w);
            *(float4*)(Bs + row * GBS + c4) = bv;
        }
        __syncthreads();

#pragma unroll
        for (int s = 0; s < 2; s++) {
            const int kk = s * 8;
            unsigned a[4][4];
#pragma unroll
            for (int i = 0; i < 4; i++) {
                int r = wm + i * 16 + g;
                a[i][0] = __float_as_uint(As[r * GAS + kk + t]);
                a[i][1] = __float_as_uint(As[(r + 8) * GAS + kk + t]);
                a[i][2] = __float_as_uint(As[r * GAS + kk + t + 4]);
                a[i][3] = __float_as_uint(As[(r + 8) * GAS + kk + t + 4]);
            }
#pragma unroll
            for (int j = 0; j < 4; j++) {
                int n = wn + j * 8 + g;
                unsigned b0 = __float_as_uint(Bs[n * GBS + kk + t]);
                unsigned b1 = __float_as_uint(Bs[n * GBS + kk + t + 4]);
#pragma unroll
                for (int i = 0; i < 4; i++)
                    mma_tf32(acc[i][j], a[i][0], a[i][1], a[i][2], a[i][3], b0, b1);
            }
        }
        __syncthreads();
    }

    // epilogue
#pragma unroll
    for (int j = 0; j < 4; j++) {
        int c0 = n0 + wn + j * 8 + t * 2;
        float b0v = bias ? bias[c0] : 0.f;
        float b1v = bias ? bias[c0 + 1] : 0.f;
#pragma unroll
        for (int i = 0; i < 4; i++) {
            int r0 = m0 + wm + i * 16 + g;
            int r1 = r0 + 8;
            if (r0 < M) {
                float2 p;
                p.x = (acc[i][j][0] + b0v) * scale;
                p.y = (acc[i][j][1] + b1v) * scale;
                *(float2*)(C + (size_t)r0 * D + c0) = p;
            }
            if (r1 < M) {
                float2 p;
                p.x = (acc[i][j][2] + b0v) * scale;
                p.y = (acc[i][j][3] + b1v) * scale;
                *(float2*)(C + (size_t)r1 * D + c0) = p;
            }
        }
    }
}

// ---------------------------------------------------------------------------
// Tensor-core flash attention (tf32).
// Block: 256 thr (8 warps), 128 queries x one head. Warp owns 16 q rows.
// K tile 64 keys. Online softmax in registers on the mma C-fragment layout.
// P (C-layout) -> A-layout via warp shuffles, no smem round trip.
// smem: Qs[128][68], Ks[64][68], Vs[64][72]  (strides chosen conflict-free)
// ---------------------------------------------------------------------------
#define QS_S 68
#define KS_S 68
#define VS_S 72
#define ATT_SMEM ((128 * QS_S + 64 * KS_S + 64 * VS_S) * 4)

__global__ void __launch_bounds__(256) attn_tc(
    const float* __restrict__ q, const float* __restrict__ k,
    const float* __restrict__ v, float* __restrict__ o)
{
    extern __shared__ float sm[];
    float* Qs = sm;                               // [128][QS_S]
    float* Ks = sm + 128 * QS_S;                  // [64][KS_S]
    float* Vs = sm + 128 * QS_S + 64 * KS_S;      // [64][VS_S]

    const int h = blockIdx.y;
    const int q0 = blockIdx.x * 128;
    const int tid = threadIdx.x;
    const int w = tid >> 5;
    const int l = tid & 31;
    const int g = l >> 2;
    const int t = l & 3;
    const int r0 = w * 16 + g;   // local q row of c-frag row 0 (row1 = r0+8)

    // Load Q tile (tf32-rounded, zero-padded)
#pragma unroll
    for (int it = 0; it < 8; it++) {
        int slot = tid + 256 * it;      // 2048 float4 slots
        int row = slot >> 4;
        int c4 = (slot & 15) * 4;
        float4 val = make_float4(0.f, 0.f, 0.f, 0.f);
        if (q0 + row < N_TOK)
            val = *(const float4*)(q + (size_t)(q0 + row) * D + h * HD + c4);
        val.x = tf32r(val.x); val.y = tf32r(val.y);
        val.z = tf32r(val.z); val.w = tf32r(val.w);
        *(float4*)(Qs + row * QS_S + c4) = val;
    }
    __syncthreads();

    float m0 = -1e30f, m1 = -1e30f, l0 = 0.f, l1 = 0.f;
    float oacc[8][4];
#pragma unroll
    for (int n = 0; n < 8; n++)
#pragma unroll
        for (int r = 0; r < 4; r++) oacc[n][r] = 0.f;

    const int srcA = (l & ~3) | (t >> 1);
    const int srcB = srcA + 2;
    const bool odd = (t & 1);

    for (int t0 = 0; t0 < N_TOK; t0 += 64) {
        const int cnt = min(64, N_TOK - t0);

        // Fill K and V tiles (zero-padded)
#pragma unroll
        for (int it = 0; it < 4; it++) {
            int slot = tid + 256 * it;   // 1024 float4 slots
            int row = slot >> 4;
            int c4 = (slot & 15) * 4;
            float4 kv = make_float4(0.f, 0.f, 0.f, 0.f);
            float4 vv = make_float4(0.f, 0.f, 0.f, 0.f);
            if (row < cnt) {
                kv = *(const float4*)(k + (size_t)(t0 + row) * D + h * HD + c4);
                vv = *(const float4*)(v + (size_t)(t0 + row) * D + h * HD + c4);
            }
            kv.x = tf32r(kv.x); kv.y = tf32r(kv.y);
            kv.z = tf32r(kv.z); kv.w = tf32r(kv.w);
            vv.x = tf32r(vv.x); vv.y = tf32r(vv.y);
            vv.z = tf32r(vv.z); vv.w = tf32r(vv.w);
            *(float4*)(Ks + row * KS_S + c4) = kv;
            *(float4*)(Vs + row * VS_S + c4) = vv;
        }
        __syncthreads();

        // S = Q @ K^T   (warp rows r0/r0+8, cols: n-tile n covers keys n*8..+8)
        float sc[8][4];
#pragma unroll
        for (int n = 0; n < 8; n++)
#pragma unroll
            for (int r = 0; r < 4; r++) sc[n][r] = 0.f;

#pragma unroll
        for (int s = 0; s < 8; s++) {
            unsigned a0 = __float_as_uint(Qs[r0 * QS_S + s * 8 + t]);
            unsigned a1 = __float_as_uint(Qs[(r0 + 8) * QS_S + s * 8 + t]);
            unsigned a2 = __float_as_uint(Qs[r0 * QS_S + s * 8 + t + 4]);
            unsigned a3 = __float_as_uint(Qs[(r0 + 8) * QS_S + s * 8 + t + 4]);
#pragma unroll
            for (int n = 0; n < 8; n++) {
                unsigned b0 = __float_as_uint(Ks[(n * 8 + g) * KS_S + s * 8 + t]);
                unsigned b1 = __float_as_uint(Ks[(n * 8 + g) * KS_S + s * 8 + t + 4]);
                mma_tf32(sc[n], a0, a1, a2, a3, b0, b1);
            }
        }

        // Mask padded keys (last tile only)
        if (cnt < 64) {
#pragma unroll
            for (int n = 0; n < 8; n++) {
                int j0 = n * 8 + t * 2;
                if (j0 >= cnt)     { sc[n][0] = -1e30f; sc[n][2] = -1e30f; }
                if (j0 + 1 >= cnt) { sc[n][1] = -1e30f; sc[n][3] = -1e30f; }
            }
        }

        // Online softmax (rows r0, r0+8)
        float mx0 = -1e30f, mx1 = -1e30f;
#pragma unroll
        for (int n = 0; n < 8; n++) {
            mx0 = fmaxf(mx0, fmaxf(sc[n][0], sc[n][1]));
            mx1 = fmaxf(mx1, fmaxf(sc[n][2], sc[n][3]));
        }
        mx0 = fmaxf(mx0, __shfl_xor_sync(0xffffffffu, mx0, 1));
        mx0 = fmaxf(mx0, __shfl_xor_sync(0xffffffffu, mx0, 2));
        mx1 = fmaxf(mx1, __shfl_xor_sync(0xffffffffu, mx1, 1));
        mx1 = fmaxf(mx1, __shfl_xor_sync(0xffffffffu, mx1, 2));
        float nm0 = fmaxf(m0, mx0), nm1 = fmaxf(m1, mx1);
        float esc0 = __expf(m0 - nm0), esc1 = __expf(m1 - nm1);
        m0 = nm0; m1 = nm1;

        float sum0 = 0.f, sum1 = 0.f;
#pragma unroll
        for (int n = 0; n < 8; n++) {
            sc[n][0] = __expf(sc[n][0] - m0);
            sc[n][1] = __expf(sc[n][1] - m0);
            sc[n][2] = __expf(sc[n][2] - m1);
            sc[n][3] = __expf(sc[n][3] - m1);
            sum0 += sc[n][0] + sc[n][1];
            sum1 += sc[n][2] + sc[n][3];
        }
        sum0 += __shfl_xor_sync(0xffffffffu, sum0, 1);
        sum0 += __shfl_xor_sync(0xffffffffu, sum0, 2);
        sum1 += __shfl_xor_sync(0xffffffffu, sum1, 1);
        sum1 += __shfl_xor_sync(0xffffffffu, sum1, 2);
        l0 = l0 * esc0 + sum0;
        l1 = l1 * esc1 + sum1;

        if (__any_sync(0xffffffffu, (esc0 != 1.f) || (esc1 != 1.f))) {
#pragma unroll
            for (int n = 0; n < 8; n++) {
                oacc[n][0] *= esc0; oacc[n][1] *= esc0;
                oacc[n][2] *= esc1; oacc[n][3] *= esc1;
            }
        }

        // O += P @ V.  A-frags for k-step s come from sc[s] via shuffles.
#pragma unroll
        for (int s = 0; s < 8; s++) {
            float v00 = __shfl_sync(0xffffffffu, sc[s][0], srcA);
            float v01 = __shfl_sync(0xffffffffu, sc[s][1], srcA);
            float v10 = __shfl_sync(0xffffffffu, sc[s][2], srcA);
            float v11 = __shfl_sync(0xffffffffu, sc[s][3], srcA);
            float w00 = __shfl_sync(0xffffffffu, sc[s][0], srcB);
            float w01 = __shfl_sync(0xffffffffu, sc[s][1], srcB);
            float w10 = __shfl_sync(0xffffffffu, sc[s][2], srcB);
            float w11 = __shfl_sync(0xffffffffu, sc[s][3], srcB);
            unsigned a0 = f2tf32(odd ? v01 : v00);
            unsigned a1 = f2tf32(odd ? v11 : v10);
            unsigned a2 = f2tf32(odd ? w01 : w00);
            unsigned a3 = f2tf32(odd ? w11 : w10);
#pragma unroll
            for (int n = 0; n < 8; n++) {
                unsigned b0 = __float_as_uint(Vs[(s * 8 + t) * VS_S + n * 8 + g]);
                unsigned b1 = __float_as_uint(Vs[(s * 8 + t + 4) * VS_S + n * 8 + g]);
                mma_tf32(oacc[n], a0, a1, a2, a3, b0, b1);
            }
        }
        __syncthreads();
    }

    // Epilogue
    float i0 = 1.f / l0, i1 = 1.f / l1;
    int gr0 = q0 + r0, gr1 = gr0 + 8;
#pragma unroll
    for (int n = 0; n < 8; n++) {
        int c = h * HD + n * 8 + t * 2;
        if (gr0 < N_TOK) {
            float2 p;
            p.x = oacc[n][0] * i0; p.y = oacc[n][1] * i0;
            *(float2*)(o + (size_t)gr0 * D + c) = p;
        }
        if (gr1 < N_TOK) {
            float2 p;
            p.x = oacc[n][2] * i1; p.y = oacc[n][3] * i1;
            *(float2*)(o + (size_t)gr1 * D + c) = p;
        }
    }
}

// ---------------------------------------------------------------------------
// LayerNorm (in place): one block per token row.
// ---------------------------------------------------------------------------
__global__ void __launch_bounds__(256) ln_kernel(
    float* __restrict__ o, const float* __restrict__ g, const float* __restrict__ b)
{
    const int row = blockIdx.x;
    float* p = o + (size_t)row * D;
    const int t = threadIdx.x;
    float x0 = p[t], x1 = p[t + 256], x2 = p[t + 512];
    float s = x0 + x1 + x2;
    float sq = x0 * x0 + x1 * x1 + x2 * x2;

    __shared__ float red[64];
#pragma unroll
    for (int off = 16; off > 0; off >>= 1) {
        s  += __shfl_down_sync(0xffffffffu, s, off);
        sq += __shfl_down_sync(0xffffffffu, sq, off);
    }
    int wid = t >> 5, lid = t & 31;
    if (lid == 0) { red[wid] = s; red[wid + 32] = sq; }
    __syncthreads();
    __shared__ float mu_s, rstd_s;
    if (t == 0) {
        float S = 0.f, SQ = 0.f;
#pragma unroll
        for (int i = 0; i < 8; i++) { S += red[i]; SQ += red[i + 32]; }
        float mu = S * (1.f / D);
        float var = SQ * (1.f / D) - mu * mu;
        mu_s = mu;
        rstd_s = rsqrtf(var + 1e-5f);
    }
    __syncthreads();
    float mu = mu_s, r = rstd_s;
    p[t]       = (x0 - mu) * r * g[t]       + b[t];
    p[t + 256] = (x1 - mu) * r * g[t + 256] + b[t + 256];
    p[t + 512] = (x2 - mu) * r * g[t + 512] + b[t + 512];
}

// ---------------------------------------------------------------------------
extern "C" void kernel_launch(void* const* d_in, const int* in_sizes, int n_in,
                              void* d_out, int out_size)
{
    const float* x    = (const float*)d_in[0];
    const float* wq_p = (const float*)d_in[1];
    const float* wk_p = (const float*)d_in[2];
    const float* wv_p = (const float*)d_in[3];
    const float* wq_d = (const float*)d_in[4];
    const float* wk_d = (const float*)d_in[5];
    const float* wv_d = (const float*)d_in[6];
    const float* bq_p = (const float*)d_in[7];
    const float* bv_p = (const float*)d_in[8];
    const float* bq_d = (const float*)d_in[9];
    const float* bv_d = (const float*)d_in[10];
    const float* ln_g = (const float*)d_in[11];
    const float* ln_b = (const float*)d_in[12];
    const float* wo_p = (const float*)d_in[13];
    const float* bo_p = (const float*)d_in[14];
    const float* wo_d = (const float*)d_in[15];
    const float* bo_d = (const float*)d_in[16];
    float* out = (float*)d_out;

    float *q, *k, *v, *o;
    cudaGetSymbolAddress((void**)&q, g_q);
    cudaGetSymbolAddress((void**)&k, g_k);
    cudaGetSymbolAddress((void**)&v, g_v);
    cudaGetSymbolAddress((void**)&o, g_o);

    cudaFuncSetAttribute(attn_tc, cudaFuncAttributeMaxDynamicSharedMemorySize, ATT_SMEM);

    const size_t OFF = (size_t)NP * D;
    dim3 gp(D / 128, (NP + 127) / 128);   // (6, 33)
    dim3 gd(D / 128, 1);                  // 100-row tail

    // QKV projections (q scaled by 1/sqrt(HD); k has no bias)
    gemm_tc<<<gp, 256>>>(x,        wq_p, bq_p, q,        NP, QSCALE);
    gemm_tc<<<gd, 256>>>(x + OFF,  wq_d, bq_d, q + OFF,  ND, QSCALE);
    gemm_tc<<<gp, 256>>>(x,        wk_p, (const float*)nullptr, k,       NP, 1.f);
    gemm_tc<<<gd, 256>>>(x + OFF,  wk_d, (const float*)nullptr, k + OFF, ND, 1.f);
    gemm_tc<<<gp, 256>>>(x,        wv_p, bv_p, v,        NP, 1.f);
    gemm_tc<<<gd, 256>>>(x + OFF,  wv_d, bv_d, v + OFF,  ND, 1.f);

    // Attention (tensor-core flash)
    dim3 ga((N_TOK + 127) / 128, H);      // (34, 12)
    attn_tc<<<ga, 256, ATT_SMEM>>>(q, k, v, o);

    // LayerNorm (in place on o)
    ln_kernel<<<N_TOK, 256>>>(o, ln_g, ln_b);

    // Output projection
    gemm_tc<<<gp, 256>>>(o,       wo_p, bo_p, out,       NP, 1.f);
    gemm_tc<<<gd, 256>>>(o + OFF, wo_d, bo_d, out + OFF, ND, 1.f);
}

// round 5
// speedup vs baseline: 4.4957x; 1.3646x over previous
#include <cuda_runtime.h>
#include <math.h>

#define N_TOK 4301
#define NP    4201
#define ND    100
#define D     768
#define H     12
#define HD    64
#define QSCALE 0.125f

// Scratch (allocation-free rule: __device__ globals)
__device__ float g_q[(size_t)N_TOK * D];
__device__ float g_k[(size_t)N_TOK * D];
__device__ float g_v[(size_t)N_TOK * D];
__device__ float g_o[(size_t)N_TOK * D];

// ---------------------------------------------------------------------------
// tf32 helpers
// ---------------------------------------------------------------------------
__device__ __forceinline__ unsigned f2tf32(float x) {
    unsigned u;
    asm("cvt.rna.tf32.f32 %0, %1;" : "=r"(u) : "f"(x));
    return u;
}
__device__ __forceinline__ float tf32r(float x) {
    return __uint_as_float(f2tf32(x));
}
__device__ __forceinline__ void mma_tf32(float* c,
    unsigned a0, unsigned a1, unsigned a2, unsigned a3,
    unsigned b0, unsigned b1)
{
    asm volatile(
        "mma.sync.aligned.m16n8k8.row.col.f32.tf32.tf32.f32 "
        "{%0,%1,%2,%3}, {%4,%5,%6,%7}, {%8,%9}, {%0,%1,%2,%3};"
        : "+f"(c[0]), "+f"(c[1]), "+f"(c[2]), "+f"(c[3])
        : "r"(a0), "r"(a1), "r"(a2), "r"(a3), "r"(b0), "r"(b1));
}

// ---------------------------------------------------------------------------
// Shared GEMM tile body: C[tile] = (A @ W^T + bias) * scale
// Block 256 thr (8 warps, 2m x 4n), tile 128x128, BK=16, reg-prefetch
// double-buffered global loads.
// ---------------------------------------------------------------------------
#define GBK 16
#define GAS 20   // As stride (floats)
#define GBS 20   // Bs stride

struct GemmSmem {
    float As[128 * GAS];
    float Bs[128 * GBS];
};

__device__ __forceinline__ void gemm_tile_body(
    const float* __restrict__ A,       // base of full A matrix (row 0)
    const float* __restrict__ W,
    const float* __restrict__ bias,    // may be null
    float* __restrict__ C,
    int m0, int n0, int M, float scale,
    GemmSmem& s)
{
    const int tid = threadIdx.x;
    const int w = tid >> 5;
    const int l = tid & 31;
    const int g = l >> 2;
    const int t = l & 3;
    const int wm = (w >> 2) * 64;
    const int wn = (w & 3) * 32;

    // per-thread load coords (2 iterations of 512 float4 slots)
    int row_[2], c4_[2];
#pragma unroll
    for (int it = 0; it < 2; it++) {
        int slot = tid + 256 * it;
        row_[it] = slot >> 2;
        c4_[it]  = (slot & 3) * 4;
    }

    float acc[4][4][4];
#pragma unroll
    for (int i = 0; i < 4; i++)
#pragma unroll
        for (int j = 0; j < 4; j++)
#pragma unroll
            for (int r = 0; r < 4; r++) acc[i][j][r] = 0.f;

    float4 pa[2], pb[2];
    // prologue: load k0 = 0
#pragma unroll
    for (int it = 0; it < 2; it++) {
        pa[it] = make_float4(0.f, 0.f, 0.f, 0.f);
        if (m0 + row_[it] < M)
            pa[it] = *(const float4*)(A + (size_t)(m0 + row_[it]) * D + c4_[it]);
        pb[it] = *(const float4*)(W + (size_t)(n0 + row_[it]) * D + c4_[it]);
    }

    for (int k0 = 0; k0 < D; k0 += GBK) {
        // store prefetched tile (tf32-rounded)
#pragma unroll
        for (int it = 0; it < 2; it++) {
            float4 av = pa[it], bv = pb[it];
            av.x = tf32r(av.x); av.y = tf32r(av.y);
            av.z = tf32r(av.z); av.w = tf32r(av.w);
            bv.x = tf32r(bv.x); bv.y = tf32r(bv.y);
            bv.z = tf32r(bv.z); bv.w = tf32r(bv.w);
            *(float4*)(s.As + row_[it] * GAS + c4_[it]) = av;
            *(float4*)(s.Bs + row_[it] * GBS + c4_[it]) = bv;
        }
        __syncthreads();

        // prefetch next tile into regs (overlaps with compute below)
        const int kn = k0 + GBK;
        if (kn < D) {
#pragma unroll
            for (int it = 0; it < 2; it++) {
                pa[it] = make_float4(0.f, 0.f, 0.f, 0.f);
                if (m0 + row_[it] < M)
                    pa[it] = *(const float4*)(A + (size_t)(m0 + row_[it]) * D + kn + c4_[it]);
                pb[it] = *(const float4*)(W + (size_t)(n0 + row_[it]) * D + kn + c4_[it]);
            }
        }

#pragma unroll
        for (int ss = 0; ss < 2; ss++) {
            const int kk = ss * 8;
            unsigned a[4][4];
#pragma unroll
            for (int i = 0; i < 4; i++) {
                int r = wm + i * 16 + g;
                a[i][0] = __float_as_uint(s.As[r * GAS + kk + t]);
                a[i][1] = __float_as_uint(s.As[(r + 8) * GAS + kk + t]);
                a[i][2] = __float_as_uint(s.As[r * GAS + kk + t + 4]);
                a[i][3] = __float_as_uint(s.As[(r + 8) * GAS + kk + t + 4]);
            }
#pragma unroll
            for (int j = 0; j < 4; j++) {
                int n = wn + j * 8 + g;
                unsigned b0 = __float_as_uint(s.Bs[n * GBS + kk + t]);
                unsigned b1 = __float_as_uint(s.Bs[n * GBS + kk + t + 4]);
#pragma unroll
                for (int i = 0; i < 4; i++)
                    mma_tf32(acc[i][j], a[i][0], a[i][1], a[i][2], a[i][3], b0, b1);
            }
        }
        __syncthreads();
    }

    // epilogue
#pragma unroll
    for (int j = 0; j < 4; j++) {
        int c0 = n0 + wn + j * 8 + t * 2;
        float b0v = bias ? bias[c0] : 0.f;
        float b1v = bias ? bias[c0 + 1] : 0.f;
#pragma unroll
        for (int i = 0; i < 4; i++) {
            int r0 = m0 + wm + i * 16 + g;
            int r1 = r0 + 8;
            if (r0 < M) {
                float2 p;
                p.x = (acc[i][j][0] + b0v) * scale;
                p.y = (acc[i][j][1] + b1v) * scale;
                *(float2*)(C + (size_t)r0 * D + c0) = p;
            }
            if (r1 < M) {
                float2 p;
                p.x = (acc[i][j][2] + b0v) * scale;
                p.y = (acc[i][j][3] + b1v) * scale;
                *(float2*)(C + (size_t)r1 * D + c0) = p;
            }
        }
    }
}

// Fused QKV: grid (6, 34, 3). y==33 is the det tile (rows 4201..4300).
// z: 0=Q (scaled), 1=K (no bias), 2=V.
__global__ void __launch_bounds__(256) qkv_gemm(
    const float* __restrict__ x,
    const float* __restrict__ wq_p, const float* __restrict__ wq_d,
    const float* __restrict__ wk_p, const float* __restrict__ wk_d,
    const float* __restrict__ wv_p, const float* __restrict__ wv_d,
    const float* __restrict__ bq_p, const float* __restrict__ bq_d,
    const float* __restrict__ bv_p, const float* __restrict__ bv_d,
    float* __restrict__ q, float* __restrict__ k, float* __restrict__ v)
{
    __shared__ GemmSmem s;
    const bool det = (blockIdx.y == gridDim.y - 1);
    const int m0 = det ? NP : blockIdx.y * 128;
    const int M  = det ? N_TOK : NP;
    const int z = blockIdx.z;

    const float* W;
    const float* bias;
    float* C;
    float scale = 1.f;
    if (z == 0) {
        W = det ? wq_d : wq_p; bias = det ? bq_d : bq_p; C = q; scale = QSCALE;
    } else if (z == 1) {
        W = det ? wk_d : wk_p; bias = nullptr; C = k;
    } else {
        W = det ? wv_d : wv_p; bias = det ? bv_d : bv_p; C = v;
    }
    gemm_tile_body(x, W, bias, C, m0, blockIdx.x * 128, M, scale, s);
}

// Fused out-projection: grid (6, 34). y==33 is the det tile.
__global__ void __launch_bounds__(256) out_gemm(
    const float* __restrict__ A,
    const float* __restrict__ wo_p, const float* __restrict__ wo_d,
    const float* __restrict__ bo_p, const float* __restrict__ bo_d,
    float* __restrict__ C)
{
    __shared__ GemmSmem s;
    const bool det = (blockIdx.y == gridDim.y - 1);
    const int m0 = det ? NP : blockIdx.y * 128;
    const int M  = det ? N_TOK : NP;
    gemm_tile_body(A, det ? wo_d : wo_p, det ? bo_d : bo_p, C,
                   m0, blockIdx.x * 128, M, 1.f, s);
}

// ---------------------------------------------------------------------------
// Tensor-core flash attention (tf32).
// Block: 256 thr (8 warps), 128 queries x one head. Warp owns 16 q rows.
// K tile 64 keys. Online softmax in registers on the mma C-fragment layout.
// P (C-layout) -> A-layout via warp shuffles, no smem round trip.
// smem: Qs[128][68], Ks[64][68], Vs[64][72]  (strides chosen conflict-free)
// ---------------------------------------------------------------------------
#define QS_S 68
#define KS_S 68
#define VS_S 72
#define ATT_SMEM ((128 * QS_S + 64 * KS_S + 64 * VS_S) * 4)

__global__ void __launch_bounds__(256) attn_tc(
    const float* __restrict__ q, const float* __restrict__ k,
    const float* __restrict__ v, float* __restrict__ o)
{
    extern __shared__ float sm[];
    float* Qs = sm;                               // [128][QS_S]
    float* Ks = sm + 128 * QS_S;                  // [64][KS_S]
    float* Vs = sm + 128 * QS_S + 64 * KS_S;      // [64][VS_S]

    const int h = blockIdx.y;
    const int q0 = blockIdx.x * 128;
    const int tid = threadIdx.x;
    const int w = tid >> 5;
    const int l = tid & 31;
    const int g = l >> 2;
    const int t = l & 3;
    const int r0 = w * 16 + g;   // local q row of c-frag row 0 (row1 = r0+8)

    // Load Q tile (tf32-rounded, zero-padded)
#pragma unroll
    for (int it = 0; it < 8; it++) {
        int slot = tid + 256 * it;      // 2048 float4 slots
        int row = slot >> 4;
        int c4 = (slot & 15) * 4;
        float4 val = make_float4(0.f, 0.f, 0.f, 0.f);
        if (q0 + row < N_TOK)
            val = *(const float4*)(q + (size_t)(q0 + row) * D + h * HD + c4);
        val.x = tf32r(val.x); val.y = tf32r(val.y);
        val.z = tf32r(val.z); val.w = tf32r(val.w);
        *(float4*)(Qs + row * QS_S + c4) = val;
    }
    __syncthreads();

    float m0 = -1e30f, m1 = -1e30f, l0 = 0.f, l1 = 0.f;
    float oacc[8][4];
#pragma unroll
    for (int n = 0; n < 8; n++)
#pragma unroll
        for (int r = 0; r < 4; r++) oacc[n][r] = 0.f;

    const int srcA = (l & ~3) | (t >> 1);
    const int srcB = srcA + 2;
    const bool odd = (t & 1);

    for (int t0 = 0; t0 < N_TOK; t0 += 64) {
        const int cnt = min(64, N_TOK - t0);

        // Fill K and V tiles (zero-padded)
#pragma unroll
        for (int it = 0; it < 4; it++) {
            int slot = tid + 256 * it;   // 1024 float4 slots
            int row = slot >> 4;
            int c4 = (slot & 15) * 4;
            float4 kv = make_float4(0.f, 0.f, 0.f, 0.f);
            float4 vv = make_float4(0.f, 0.f, 0.f, 0.f);
            if (row < cnt) {
                kv = *(const float4*)(k + (size_t)(t0 + row) * D + h * HD + c4);
                vv = *(const float4*)(v + (size_t)(t0 + row) * D + h * HD + c4);
            }
            kv.x = tf32r(kv.x); kv.y = tf32r(kv.y);
            kv.z = tf32r(kv.z); kv.w = tf32r(kv.w);
            vv.x = tf32r(vv.x); vv.y = tf32r(vv.y);
            vv.z = tf32r(vv.z); vv.w = tf32r(vv.w);
            *(float4*)(Ks + row * KS_S + c4) = kv;
            *(float4*)(Vs + row * VS_S + c4) = vv;
        }
        __syncthreads();

        // S = Q @ K^T   (warp rows r0/r0+8, cols: n-tile n covers keys n*8..+8)
        float sc[8][4];
#pragma unroll
        for (int n = 0; n < 8; n++)
#pragma unroll
            for (int r = 0; r < 4; r++) sc[n][r] = 0.f;

#pragma unroll
        for (int s = 0; s < 8; s++) {
            unsigned a0 = __float_as_uint(Qs[r0 * QS_S + s * 8 + t]);
            unsigned a1 = __float_as_uint(Qs[(r0 + 8) * QS_S + s * 8 + t]);
            unsigned a2 = __float_as_uint(Qs[r0 * QS_S + s * 8 + t + 4]);
            unsigned a3 = __float_as_uint(Qs[(r0 + 8) * QS_S + s * 8 + t + 4]);
#pragma unroll
            for (int n = 0; n < 8; n++) {
                unsigned b0 = __float_as_uint(Ks[(n * 8 + g) * KS_S + s * 8 + t]);
                unsigned b1 = __float_as_uint(Ks[(n * 8 + g) * KS_S + s * 8 + t + 4]);
                mma_tf32(sc[n], a0, a1, a2, a3, b0, b1);
            }
        }

        // Mask padded keys (last tile only)
        if (cnt < 64) {
#pragma unroll
            for (int n = 0; n < 8; n++) {
                int j0 = n * 8 + t * 2;
                if (j0 >= cnt)     { sc[n][0] = -1e30f; sc[n][2] = -1e30f; }
                if (j0 + 1 >= cnt) { sc[n][1] = -1e30f; sc[n][3] = -1e30f; }
            }
        }

        // Online softmax (rows r0, r0+8)
        float mx0 = -1e30f, mx1 = -1e30f;
#pragma unroll
        for (int n = 0; n < 8; n++) {
            mx0 = fmaxf(mx0, fmaxf(sc[n][0], sc[n][1]));
            mx1 = fmaxf(mx1, fmaxf(sc[n][2], sc[n][3]));
        }
        mx0 = fmaxf(mx0, __shfl_xor_sync(0xffffffffu, mx0, 1));
        mx0 = fmaxf(mx0, __shfl_xor_sync(0xffffffffu, mx0, 2));
        mx1 = fmaxf(mx1, __shfl_xor_sync(0xffffffffu, mx1, 1));
        mx1 = fmaxf(mx1, __shfl_xor_sync(0xffffffffu, mx1, 2));
        float nm0 = fmaxf(m0, mx0), nm1 = fmaxf(m1, mx1);
        float esc0 = __expf(m0 - nm0), esc1 = __expf(m1 - nm1);
        m0 = nm0; m1 = nm1;

        float sum0 = 0.f, sum1 = 0.f;
#pragma unroll
        for (int n = 0; n < 8; n++) {
            sc[n][0] = __expf(sc[n][0] - m0);
            sc[n][1] = __expf(sc[n][1] - m0);
            sc[n][2] = __expf(sc[n][2] - m1);
            sc[n][3] = __expf(sc[n][3] - m1);
            sum0 += sc[n][0] + sc[n][1];
            sum1 += sc[n][2] + sc[n][3];
        }
        sum0 += __shfl_xor_sync(0xffffffffu, sum0, 1);
        sum0 += __shfl_xor_sync(0xffffffffu, sum0, 2);
        sum1 += __shfl_xor_sync(0xffffffffu, sum1, 1);
        sum1 += __shfl_xor_sync(0xffffffffu, sum1, 2);
        l0 = l0 * esc0 + sum0;
        l1 = l1 * esc1 + sum1;

        if (__any_sync(0xffffffffu, (esc0 != 1.f) || (esc1 != 1.f))) {
#pragma unroll
            for (int n = 0; n < 8; n++) {
                oacc[n][0] *= esc0; oacc[n][1] *= esc0;
                oacc[n][2] *= esc1; oacc[n][3] *= esc1;
            }
        }

        // O += P @ V.  A-frags for k-step s come from sc[s] via shuffles.
#pragma unroll
        for (int s = 0; s < 8; s++) {
            float v00 = __shfl_sync(0xffffffffu, sc[s][0], srcA);
            float v01 = __shfl_sync(0xffffffffu, sc[s][1], srcA);
            float v10 = __shfl_sync(0xffffffffu, sc[s][2], srcA);
            float v11 = __shfl_sync(0xffffffffu, sc[s][3], srcA);
            float w00 = __shfl_sync(0xffffffffu, sc[s][0], srcB);
            float w01 = __shfl_sync(0xffffffffu, sc[s][1], srcB);
            float w10 = __shfl_sync(0xffffffffu, sc[s][2], srcB);
            float w11 = __shfl_sync(0xffffffffu, sc[s][3], srcB);
            unsigned a0 = f2tf32(odd ? v01 : v00);
            unsigned a1 = f2tf32(odd ? v11 : v10);
            unsigned a2 = f2tf32(odd ? w01 : w00);
            unsigned a3 = f2tf32(odd ? w11 : w10);
#pragma unroll
            for (int n = 0; n < 8; n++) {
                unsigned b0 = __float_as_uint(Vs[(s * 8 + t) * VS_S + n * 8 + g]);
                unsigned b1 = __float_as_uint(Vs[(s * 8 + t + 4) * VS_S + n * 8 + g]);
                mma_tf32(oacc[n], a0, a1, a2, a3, b0, b1);
            }
        }
        __syncthreads();
    }

    // Epilogue
    float i0 = 1.f / l0, i1 = 1.f / l1;
    int gr0 = q0 + r0, gr1 = gr0 + 8;
#pragma unroll
    for (int n = 0; n < 8; n++) {
        int c = h * HD + n * 8 + t * 2;
        if (gr0 < N_TOK) {
            float2 p;
            p.x = oacc[n][0] * i0; p.y = oacc[n][1] * i0;
            *(float2*)(o + (size_t)gr0 * D + c) = p;
        }
        if (gr1 < N_TOK) {
            float2 p;
            p.x = oacc[n][2] * i1; p.y = oacc[n][3] * i1;
            *(float2*)(o + (size_t)gr1 * D + c) = p;
        }
    }
}

// ---------------------------------------------------------------------------
// LayerNorm (in place): one block per token row.
// ---------------------------------------------------------------------------
__global__ void __launch_bounds__(256) ln_kernel(
    float* __restrict__ o, const float* __restrict__ g, const float* __restrict__ b)
{
    const int row = blockIdx.x;
    float* p = o + (size_t)row * D;
    const int t = threadIdx.x;
    float x0 = p[t], x1 = p[t + 256], x2 = p[t + 512];
    float s = x0 + x1 + x2;
    float sq = x0 * x0 + x1 * x1 + x2 * x2;

    __shared__ float red[64];
#pragma unroll
    for (int off = 16; off > 0; off >>= 1) {
        s  += __shfl_down_sync(0xffffffffu, s, off);
        sq += __shfl_down_sync(0xffffffffu, sq, off);
    }
    int wid = t >> 5, lid = t & 31;
    if (lid == 0) { red[wid] = s; red[wid + 32] = sq; }
    __syncthreads();
    __shared__ float mu_s, rstd_s;
    if (t == 0) {
        float S = 0.f, SQ = 0.f;
#pragma unroll
        for (int i = 0; i < 8; i++) { S += red[i]; SQ += red[i + 32]; }
        float mu = S * (1.f / D);
        float var = SQ * (1.f / D) - mu * mu;
        mu_s = mu;
        rstd_s = rsqrtf(var + 1e-5f);
    }
    __syncthreads();
    float mu = mu_s, r = rstd_s;
    p[t]       = (x0 - mu) * r * g[t]       + b[t];
    p[t + 256] = (x1 - mu) * r * g[t + 256] + b[t + 256];
    p[t + 512] = (x2 - mu) * r * g[t + 512] + b[t + 512];
}

// ---------------------------------------------------------------------------
extern "C" void kernel_launch(void* const* d_in, const int* in_sizes, int n_in,
                              void* d_out, int out_size)
{
    const float* x    = (const float*)d_in[0];
    const float* wq_p = (const float*)d_in[1];
    const float* wk_p = (const float*)d_in[2];
    const float* wv_p = (const float*)d_in[3];
    const float* wq_d = (const float*)d_in[4];
    const float* wk_d = (const float*)d_in[5];
    const float* wv_d = (const float*)d_in[6];
    const float* bq_p = (const float*)d_in[7];
    const float* bv_p = (const float*)d_in[8];
    const float* bq_d = (const float*)d_in[9];
    const float* bv_d = (const float*)d_in[10];
    const float* ln_g = (const float*)d_in[11];
    const float* ln_b = (const float*)d_in[12];
    const float* wo_p = (const float*)d_in[13];
    const float* bo_p = (const float*)d_in[14];
    const float* wo_d = (const float*)d_in[15];
    const float* bo_d = (const float*)d_in[16];
    float* out = (float*)d_out;

    float *q, *k, *v, *o;
    cudaGetSymbolAddress((void**)&q, g_q);
    cudaGetSymbolAddress((void**)&k, g_k);
    cudaGetSymbolAddress((void**)&v, g_v);
    cudaGetSymbolAddress((void**)&o, g_o);

    cudaFuncSetAttribute(attn_tc, cudaFuncAttributeMaxDynamicSharedMemorySize, ATT_SMEM);

    // Fused QKV projections: 6 x 34 x 3 = 612 blocks, one launch.
    dim3 gq(D / 128, 34, 3);
    qkv_gemm<<<gq, 256>>>(x, wq_p, wq_d, wk_p, wk_d, wv_p, wv_d,
                          bq_p, bq_d, bv_p, bv_d, q, k, v);

    // Attention (tensor-core flash)
    dim3 ga((N_TOK + 127) / 128, H);      // (34, 12)
    attn_tc<<<ga, 256, ATT_SMEM>>>(q, k, v, o);

    // LayerNorm (in place on o)
    ln_kernel<<<N_TOK, 256>>>(o, ln_g, ln_b);

    // Output projection (patch + det fused)
    dim3 go(D / 128, 34);
    out_gemm<<<go, 256>>>(o, wo_p, wo_d, bo_p, bo_d, out);
}